// round 17
// baseline (speedup 1.0000x reference)
#include <cuda_runtime.h>
#include <cuda_fp16.h>
#include <cstdint>

// ---------------------------------------------------------------------------
// Banded causal attention (Longformer w=128, window 256, D=64) on mma.sync
// fp16 HMMA, flash-online softmax. 512-thread CTA: warp pair (2p,2p+1) co-owns
// one 16-row block, splitting column tile-pairs by parity -> each warp reads
// HALF the K/V smem tiles (L1 traffic halved). Two-way flash merge at end.
// K hi/lo + V in smem; Q direct to fragments. 1 CTA/SM, 16 warps, <=128 regs.
// ---------------------------------------------------------------------------

#define KHI 0u
#define KLO 36864u
#define VHI 73728u
#define AMS 110592u
#define OEX 111616u          // 8 pairs x 4KB fp32 o-exchange
#define MSX 144384u          // 8 pairs x 512B m/s exchange
#define SMEM_TOTAL 148480

#define LOG2E 1.4426950408889634f

static __device__ __forceinline__ uint32_t smem_u32(const void* p) {
    uint32_t a;
    asm("{ .reg .u64 t; cvta.to.shared.u64 t, %1; cvt.u32.u64 %0, t; }"
        : "=r"(a) : "l"(p));
    return a;
}
static __device__ __forceinline__ uint32_t packh(float lo, float hi) {
    uint32_t r;
    asm("cvt.rn.f16x2.f32 %0, %1, %2;" : "=r"(r) : "f"(hi), "f"(lo));
    return r;
}
static __device__ __forceinline__ float lowf(uint32_t u) {
    return __half2float(__ushort_as_half((unsigned short)(u & 0xffffu)));
}
static __device__ __forceinline__ float highf(uint32_t u) {
    return __half2float(__ushort_as_half((unsigned short)(u >> 16)));
}
static __device__ __forceinline__ float ex2f(float x) {
    float y;
    asm("ex2.approx.ftz.f32 %0, %1;" : "=f"(y) : "f"(x));
    return y;
}
static __device__ __forceinline__ void ldsm4(uint32_t r[4], uint32_t a) {
    asm volatile("ldmatrix.sync.aligned.m8n8.x4.shared.b16 {%0,%1,%2,%3}, [%4];"
                 : "=r"(r[0]), "=r"(r[1]), "=r"(r[2]), "=r"(r[3]) : "r"(a));
}
static __device__ __forceinline__ void ldsm4t(uint32_t r[4], uint32_t a) {
    asm volatile("ldmatrix.sync.aligned.m8n8.x4.trans.shared.b16 {%0,%1,%2,%3}, [%4];"
                 : "=r"(r[0]), "=r"(r[1]), "=r"(r[2]), "=r"(r[3]) : "r"(a));
}
static __device__ __forceinline__ void mma(float d[4], const uint32_t a[4],
                                           uint32_t b0, uint32_t b1) {
    asm volatile(
        "mma.sync.aligned.m16n8k16.row.col.f32.f16.f16.f32 "
        "{%0,%1,%2,%3}, {%4,%5,%6,%7}, {%8,%9}, {%0,%1,%2,%3};"
        : "+f"(d[0]), "+f"(d[1]), "+f"(d[2]), "+f"(d[3])
        : "r"(a[0]), "r"(a[1]), "r"(a[2]), "r"(a[3]), "r"(b0), "r"(b1));
}
static __device__ __forceinline__ void split4(float4 v, uint32_t& h0, uint32_t& h1,
                                              uint32_t& l0, uint32_t& l1) {
    h0 = packh(v.x, v.y);
    h1 = packh(v.z, v.w);
    l0 = packh(v.x - lowf(h0), v.y - highf(h0));
    l1 = packh(v.z - lowf(h1), v.w - highf(h1));
}
static __device__ __forceinline__ void split2s(float2 v, uint32_t& h, uint32_t& l) {
    float x = v.x * LOG2E, y = v.y * LOG2E;
    h = packh(x, y);
    l = packh(x - lowf(h), y - highf(h));
}

__global__ __launch_bounds__(512, 1)
void lf_hmma_kernel(const float* __restrict__ Q, const float* __restrict__ K,
                    const float* __restrict__ V, const float* __restrict__ AM,
                    float* __restrict__ O, int S) {
    extern __shared__ char sm[];
    const uint32_t sb = smem_u32(sm);
    const int tid  = threadIdx.x;
    const int w    = tid >> 5;
    const int lane = tid & 31;
    const int g    = lane >> 2;
    const int tg   = lane & 3;
    const int p    = w >> 1;                        // pair id 0..7
    const int c    = w & 1;                         // column parity
    const int rb   = (int)((0x54236710u >> (p * 4)) & 0xFu);  // SMSP-balanced
    const int h    = blockIdx.y;
    const int q0   = blockIdx.x << 7;
    const int kb   = q0 - 128;
    const bool blk0 = (q0 == 0);

    const float* Qg = Q + ((size_t)h * S + q0) * 64;
    const float* Kg = K + (size_t)h * S * 64;
    const float* Vg = V + (size_t)h * S * 64;

    // ---- stage K (hi/lo) and V (hi) + mask*log2e into smem ----
#pragma unroll
    for (int it = 0; it < 8; ++it) {
        int idx = it * 512 + tid, y = idx >> 4, c4 = idx & 15;
        float4 kv = make_float4(0.f, 0.f, 0.f, 0.f);
        float4 vv = make_float4(0.f, 0.f, 0.f, 0.f);
        if (!blk0 || y >= 128) {
            kv = *reinterpret_cast<const float4*>(Kg + (size_t)(kb + y) * 64 + c4 * 4);
            vv = *reinterpret_cast<const float4*>(Vg + (size_t)(kb + y) * 64 + c4 * 4);
        }
        uint32_t off = (uint32_t)y * 144u + (uint32_t)c4 * 8u;
        uint32_t h0, h1, l0, l1; split4(kv, h0, h1, l0, l1);
        *reinterpret_cast<uint2*>(sm + KHI + off) = make_uint2(h0, h1);
        *reinterpret_cast<uint2*>(sm + KLO + off) = make_uint2(l0, l1);
        h0 = packh(vv.x, vv.y); h1 = packh(vv.z, vv.w);
        *reinterpret_cast<uint2*>(sm + VHI + off) = make_uint2(h0, h1);
    }
    if (tid < 256) {
        float am = 0.f;
        if (!blk0 || tid >= 128) am = AM[kb + tid] * LOG2E;
        reinterpret_cast<float*>(sm + AMS)[tid] = am;
    }

    // ---- Q fragments direct from global (scaled by log2e, hi/lo split) ----
    const int r0 = rb * 16 + g;
    uint32_t aqh[4][4], aql[4][4];
    {
        const float* Qr0 = Qg + (size_t)r0 * 64 + 2 * tg;
        const float* Qr8 = Qr0 + 8 * 64;
#pragma unroll
        for (int ks = 0; ks < 4; ++ks) {
            float2 q00 = *reinterpret_cast<const float2*>(Qr0 + 16 * ks);
            float2 q10 = *reinterpret_cast<const float2*>(Qr8 + 16 * ks);
            float2 q08 = *reinterpret_cast<const float2*>(Qr0 + 16 * ks + 8);
            float2 q18 = *reinterpret_cast<const float2*>(Qr8 + 16 * ks + 8);
            split2s(q00, aqh[ks][0], aql[ks][0]);
            split2s(q10, aqh[ks][1], aql[ks][1]);
            split2s(q08, aqh[ks][2], aql[ks][2]);
            split2s(q18, aqh[ks][3], aql[ks][3]);
        }
    }
    __syncthreads();

    const int ilo = blk0 ? 8 : 0;      // first valid tile-pair index
    const int ib  = 8 + rb;            // boundary tile-pair (last valid)

    const int lim0 = 128 + r0, lim1 = lim0 + 8;
    const float* AMsm = reinterpret_cast<const float*>(sm + AMS);

    const uint32_t kb_h = sb + KHI + (uint32_t)(lane & 7) * 144u +
                          (uint32_t)((lane >> 3) & 3) * 16u;
    const uint32_t kb_l = kb_h + (KLO - KHI);
    const uint32_t vb_h = sb + VHI +
        (uint32_t)(((lane >> 3) & 1) * 8 + (lane & 7)) * 144u +
        (uint32_t)((lane >> 4) & 1) * 16u;

    float m0 = -1e30f, m1 = -1e30f;
    float s0 = 0.f, s1 = 0.f;
    float o[8][4];
#pragma unroll
    for (int i = 0; i < 8; ++i) { o[i][0] = o[i][1] = o[i][2] = o[i][3] = 0.f; }

    // ---- fused flash loop over this warp's parity of tile pairs ----
#pragma unroll
    for (int nt = 0; nt < 32; nt += 2) {
        const int i = nt >> 1;
        if (((i & 1) != c) || i < ilo || i > ib) continue;
        float dA0[4] = {0,0,0,0}, dB0[4] = {0,0,0,0};
        float dA1[4] = {0,0,0,0}, dB1[4] = {0,0,0,0};
#pragma unroll
        for (int ph = 0; ph < 2; ++ph) {
            uint32_t bh[4], bl[4], ch[4], cl[4];
            ldsm4(bh, kb_h + (uint32_t)nt * 8u * 144u + ph * 64);
            ldsm4(bl, kb_l + (uint32_t)nt * 8u * 144u + ph * 64);
            ldsm4(ch, kb_h + (uint32_t)(nt + 1) * 8u * 144u + ph * 64);
            ldsm4(cl, kb_l + (uint32_t)(nt + 1) * 8u * 144u + ph * 64);
            const int k0 = 2 * ph, k1 = 2 * ph + 1;
            mma(dA0, aqh[k0], bh[0], bh[1]);
            mma(dA1, aqh[k0], ch[0], ch[1]);
            mma(dB0, aqh[k0], bl[0], bl[1]);
            mma(dB1, aqh[k0], cl[0], cl[1]);
            mma(dA0, aqh[k1], bh[2], bh[3]);
            mma(dA1, aqh[k1], ch[2], ch[3]);
            mma(dB0, aqh[k1], bl[2], bl[3]);
            mma(dB1, aqh[k1], cl[2], cl[3]);
            if (ph == 0) {
                mma(dA0, aql[k0], bh[0], bh[1]);
                mma(dA1, aql[k0], ch[0], ch[1]);
                mma(dA0, aql[k1], bh[2], bh[3]);
                mma(dA1, aql[k1], ch[2], ch[3]);
            } else {
                mma(dB0, aql[k0], bh[0], bh[1]);
                mma(dB1, aql[k0], ch[0], ch[1]);
                mma(dB0, aql[k1], bh[2], bh[3]);
                mma(dB1, aql[k1], ch[2], ch[3]);
            }
        }
        // ---- epilogue: mask fold (+ causal on boundary pair) ----
        int col0 = nt * 8 + 2 * tg;
        float am0 = AMsm[col0],     am1 = AMsm[col0 + 1];
        float bm0 = AMsm[col0 + 8], bm1 = AMsm[col0 + 9];
        float v0, v1, v2, v3, u0, u1, u2, u3;
        if (i < ib) {
            v0 = dA0[0] + dB0[0] + am0;
            v1 = dA0[1] + dB0[1] + am1;
            v2 = dA0[2] + dB0[2] + am0;
            v3 = dA0[3] + dB0[3] + am1;
            u0 = dA1[0] + dB1[0] + bm0;
            u1 = dA1[1] + dB1[1] + bm1;
            u2 = dA1[2] + dB1[2] + bm0;
            u3 = dA1[3] + dB1[3] + bm1;
        } else {
            int c1 = col0 + 1, c8 = col0 + 8, c9 = col0 + 9;
            v0 = (col0 <= lim0) ? dA0[0] + dB0[0] + am0 : -1e30f;
            v1 = (c1   <= lim0) ? dA0[1] + dB0[1] + am1 : -1e30f;
            v2 = (col0 <= lim1) ? dA0[2] + dB0[2] + am0 : -1e30f;
            v3 = (c1   <= lim1) ? dA0[3] + dB0[3] + am1 : -1e30f;
            u0 = (c8   <= lim0) ? dA1[0] + dB1[0] + bm0 : -1e30f;
            u1 = (c9   <= lim0) ? dA1[1] + dB1[1] + bm1 : -1e30f;
            u2 = (c8   <= lim1) ? dA1[2] + dB1[2] + bm0 : -1e30f;
            u3 = (c9   <= lim1) ? dA1[3] + dB1[3] + bm1 : -1e30f;
        }
        // ---- per-quad online max + rescale ----
        float pm0 = fmaxf(fmaxf(v0, v1), fmaxf(u0, u1));
        float pm1 = fmaxf(fmaxf(v2, v3), fmaxf(u2, u3));
        pm0 = fmaxf(pm0, __shfl_xor_sync(0xffffffffu, pm0, 1));
        pm0 = fmaxf(pm0, __shfl_xor_sync(0xffffffffu, pm0, 2));
        pm1 = fmaxf(pm1, __shfl_xor_sync(0xffffffffu, pm1, 1));
        pm1 = fmaxf(pm1, __shfl_xor_sync(0xffffffffu, pm1, 2));
        float n0 = fmaxf(m0, pm0), n1 = fmaxf(m1, pm1);
        float rs0 = ex2f(m0 - n0), rs1 = ex2f(m1 - n1);
        m0 = n0; m1 = n1;
        s0 *= rs0; s1 *= rs1;
#pragma unroll
        for (int j = 0; j < 8; ++j) {
            o[j][0] *= rs0; o[j][1] *= rs0;
            o[j][2] *= rs1; o[j][3] *= rs1;
        }
        // ---- exp + sum + pack ----
        float e0 = ex2f(v0 - m0), e1 = ex2f(v1 - m0);
        float e2 = ex2f(v2 - m1), e3 = ex2f(v3 - m1);
        float f0 = ex2f(u0 - m0), f1 = ex2f(u1 - m0);
        float f2 = ex2f(u2 - m1), f3 = ex2f(u3 - m1);
        s0 += (e0 + e1) + (f0 + f1);
        s1 += (e2 + e3) + (f2 + f3);
        uint32_t ah[4];
        ah[0] = packh(e0, e1);
        ah[1] = packh(e2, e3);
        ah[2] = packh(f0, f1);
        ah[3] = packh(f2, f3);
        // ---- PV for this k-tile ----
#pragma unroll
        for (int dp = 0; dp < 4; ++dp) {
            uint32_t bh[4];
            ldsm4t(bh, vb_h + (uint32_t)i * 16u * 144u + dp * 32);
            mma(o[2*dp],     ah, bh[0], bh[1]);
            mma(o[2*dp + 1], ah, bh[2], bh[3]);
        }
    }

    // ---- pairwise flash merge: parity 1 publishes, parity 0 merges ----
    float* oex = reinterpret_cast<float*>(sm + OEX) + p * 1024;
    float* msx = reinterpret_cast<float*>(sm + MSX) + p * 128;
    if (c == 1) {
#pragma unroll
        for (int j = 0; j < 8; ++j) {
            oex[(4*j + 0) * 32 + lane] = o[j][0];
            oex[(4*j + 1) * 32 + lane] = o[j][1];
            oex[(4*j + 2) * 32 + lane] = o[j][2];
            oex[(4*j + 3) * 32 + lane] = o[j][3];
        }
        msx[0 * 32 + lane] = m0;
        msx[1 * 32 + lane] = m1;
        msx[2 * 32 + lane] = s0;
        msx[3 * 32 + lane] = s1;
    }
    __syncthreads();
    if (c == 0) {
        float qm0 = msx[0 * 32 + lane], qm1 = msx[1 * 32 + lane];
        float qs0 = msx[2 * 32 + lane], qs1 = msx[3 * 32 + lane];
        float M0 = fmaxf(m0, qm0), M1 = fmaxf(m1, qm1);
        float a0 = ex2f(m0 - M0),  b0 = ex2f(qm0 - M0);
        float a1 = ex2f(m1 - M1),  b1 = ex2f(qm1 - M1);
        s0 = s0 * a0 + qs0 * b0;
        s1 = s1 * a1 + qs1 * b1;
        s0 += __shfl_xor_sync(0xffffffffu, s0, 1);
        s0 += __shfl_xor_sync(0xffffffffu, s0, 2);
        s1 += __shfl_xor_sync(0xffffffffu, s1, 1);
        s1 += __shfl_xor_sync(0xffffffffu, s1, 2);
        const float inv0 = __frcp_rn(s0);
        const float inv1 = __frcp_rn(s1);

        float* Ob = O + ((size_t)h * S + q0 + r0) * 64;
#pragma unroll
        for (int j = 0; j < 8; ++j) {
            int d = j * 8 + 2 * tg;
            float t0 = (o[j][0] * a0 + oex[(4*j + 0) * 32 + lane] * b0) * inv0;
            float t1 = (o[j][1] * a0 + oex[(4*j + 1) * 32 + lane] * b0) * inv0;
            float t2 = (o[j][2] * a1 + oex[(4*j + 2) * 32 + lane] * b1) * inv1;
            float t3 = (o[j][3] * a1 + oex[(4*j + 3) * 32 + lane] * b1) * inv1;
            *reinterpret_cast<float2*>(Ob + d)          = make_float2(t0, t1);
            *reinterpret_cast<float2*>(Ob + 8 * 64 + d) = make_float2(t2, t3);
        }
    }
}

extern "C" void kernel_launch(void* const* d_in, const int* in_sizes, int n_in,
                              void* d_out, int out_size) {
    const float* Q  = (const float*)d_in[0];
    const float* K  = (const float*)d_in[1];
    const float* V  = (const float*)d_in[2];
    const float* AM = (const float*)d_in[3];
    float* O = (float*)d_out;

    const int S  = in_sizes[3];
    const int BH = in_sizes[0] / (S * 64);

    cudaFuncSetAttribute(lf_hmma_kernel,
                         cudaFuncAttributeMaxDynamicSharedMemorySize, SMEM_TOTAL);

    dim3 grid(S / 128, BH);
    lf_hmma_kernel<<<grid, 512, SMEM_TOTAL>>>(Q, K, V, AM, O, S);
}